// round 7
// baseline (speedup 1.0000x reference)
#include <cuda_runtime.h>
#include <cuda_fp16.h>

#define ACTIVE     32
#define HIDDEN     256
#define ACCDIM     512
#define NTHREADS   256
#define NWARPS     (NTHREADS / 32)
#define INPUTSZ    40960
#define POSPW      4               // positions per warp pass

__device__ __forceinline__ unsigned int h2_to_u32(__half2 h) {
    return *reinterpret_cast<unsigned int*>(&h);
}
__device__ __forceinline__ __half2 u32_to_h2(unsigned int u) {
    return *reinterpret_cast<__half2*>(&u);
}
__device__ __forceinline__ float satf(float x) { return __saturatef(x); }

// packed f32x2 FMA (sm_100a; ptxas never emits from C++)
__device__ __forceinline__ void fma_f32x2(unsigned long long& d,
                                          unsigned long long a,
                                          unsigned long long b) {
    asm("fma.rn.f32x2 %0, %1, %2, %0;" : "+l"(d) : "l"(a), "l"(b));
}
__device__ __forceinline__ unsigned long long pack_f32x2(float lo, float hi) {
    unsigned long long v;
    asm("mov.b64 %0, {%1, %2};" : "=l"(v) : "r"(__float_as_uint(lo)), "r"(__float_as_uint(hi)));
    return v;
}
__device__ __forceinline__ float f32x2_hsum(unsigned long long v) {
    unsigned int lo, hi;
    asm("mov.b64 {%0,%1}, %2;" : "=r"(lo), "=r"(hi) : "l"(v));
    return __uint_as_float(lo) + __uint_as_float(hi);
}

// fp16 shadow of ft_w: 40960 rows x 256 halves = 512B/row = 32 uint4 per row.
__device__ uint4 g_ftw_h[INPUTSZ * 32];
// l1_w transposed+packed fp16: [j4][k] -> 4 halves (cols 4j4..4j4+3 of row k)
__device__ uint2 g_l1w_h[128 * 32];

// dynamic smem (per CTA):
//   sh_w1h : 128*32 uint2  (32 KB)   packed fp16 L1 weights
//   sh_l2t : 32*32  float  ( 4 KB)   l2_w transposed [j][k]
//   sh_acc : NWARPS*POSPW*512 float (64 KB)  POSPW acc vectors per warp
#define SMEM_W1H_U2  (128 * 32)
#define SMEM_L2T     (32 * 32)
#define SMEM_ACC     (NWARPS * POSPW * ACCDIM)
#define SMEM_BYTES   (SMEM_W1H_U2 * 8 + (SMEM_L2T + SMEM_ACC) * 4)

// ---------- conversion kernels (every call; deterministic) ----------
__global__ void convert_ftw_kernel(const float* __restrict__ ft_w, int n_u4)
{
    int i = blockIdx.x * blockDim.x + threadIdx.x;
    if (i >= n_u4) return;
    const float4* src = (const float4*)ft_w;
    float4 a = src[2 * i];
    float4 b = src[2 * i + 1];
    uint4 o;
    o.x = h2_to_u32(__floats2half2_rn(a.x, a.y));
    o.y = h2_to_u32(__floats2half2_rn(a.z, a.w));
    o.z = h2_to_u32(__floats2half2_rn(b.x, b.y));
    o.w = h2_to_u32(__floats2half2_rn(b.z, b.w));
    g_ftw_h[i] = o;
}

__global__ void pack_l1w_kernel(const float* __restrict__ l1_w)
{
    int i = blockIdx.x * blockDim.x + threadIdx.x;      // i = j4*32 + k
    if (i >= 128 * 32) return;
    int j4 = i >> 5, k = i & 31;
    const float* r = l1_w + k * ACCDIM + j4 * 4;
    uint2 o;
    o.x = h2_to_u32(__floats2half2_rn(r[0], r[1]));
    o.y = h2_to_u32(__floats2half2_rn(r[2], r[3]));
    g_l1w_h[i] = o;
}

// ---------- main fused kernel ----------
__global__ __launch_bounds__(NTHREADS, 2)
void nnue_fused_kernel(
    const int*   __restrict__ white_idx,
    const int*   __restrict__ black_idx,
    const float* __restrict__ stm,
    const float* __restrict__ ft_b,
    const float* __restrict__ l2_w,
    const float* __restrict__ l1_b,
    const float* __restrict__ l2_b,
    const float* __restrict__ l3_w,
    const float* __restrict__ l3_b,
    float*       __restrict__ out,
    int B)
{
    extern __shared__ float sm[];
    uint2* sh_w1h = (uint2*)sm;                           // [128][32]
    float* sh_l2t = sm + SMEM_W1H_U2 * 2;                 // [32][32]
    float* sh_acc = sh_l2t + SMEM_L2T;

    const int tid = threadIdx.x;

    for (int i = tid; i < SMEM_W1H_U2; i += NTHREADS)
        sh_w1h[i] = g_l1w_h[i];
    for (int i = tid; i < SMEM_L2T; i += NTHREADS) {
        int j = i >> 5, k = i & 31;
        sh_l2t[i] = l2_w[k * 32 + j];
    }
    __syncthreads();

    const int lane  = tid & 31;
    const int warp  = tid >> 5;
    const int gwarp = blockIdx.x * NWARPS + warp;
    const int wstride = gridDim.x * NWARPS;

    float4* accbase = (float4*)(sh_acc + warp * POSPW * ACCDIM);  // 4 x 128 float4

    const float l1b = l1_b[lane];
    const float l2b = l2_b[lane];
    const float l3w = l3_w[lane];
    const float l3b = l3_b[0];
    const float4* ftb4 = (const float4*)ft_b;
    const float4 fbA = ftb4[2 * lane];
    const float4 fbB = ftb4[2 * lane + 1];

    const int G = (B + POSPW - 1) / POSPW;

    for (int g = gwarp; g < G; g += wstride) {
        const int pbase = g * POSPW;

        // ---- feature transform + select, POSPW positions ----
        #pragma unroll 1
        for (int pp = 0; pp < POSPW; pp++) {
            const int pos = pbase + pp;
            if (pos >= B) break;
            float4* accp = accbase + pp * (ACCDIM / 4);

            const int wi = white_idx[pos * ACTIVE + lane];
            const int bi = black_idx[pos * ACTIVE + lane];

            float w0=0.f,w1=0.f,w2=0.f,w3=0.f,w4=0.f,w5=0.f,w6=0.f,w7=0.f;
            float b0=0.f,b1=0.f,b2=0.f,b3=0.f,b4=0.f,b5=0.f,b6=0.f,b7=0.f;

            const __half2 hz = u32_to_h2(0u);

            #pragma unroll
            for (int c = 0; c < 8; c++) {
                __half2 sw0=hz, sw1=hz, sw2=hz, sw3=hz;
                __half2 sb0=hz, sb1=hz, sb2=hz, sb3=hz;
                #pragma unroll
                for (int u = 0; u < 4; u++) {
                    const int j = c * 4 + u;
                    const int iw = __shfl_sync(0xffffffffu, wi, j);
                    const int ib = __shfl_sync(0xffffffffu, bi, j);
                    const uint4 rw = __ldcg(&g_ftw_h[(long)iw * 32 + lane]);
                    const uint4 rb = __ldcg(&g_ftw_h[(long)ib * 32 + lane]);
                    sw0 = __hadd2(sw0, u32_to_h2(rw.x));
                    sw1 = __hadd2(sw1, u32_to_h2(rw.y));
                    sw2 = __hadd2(sw2, u32_to_h2(rw.z));
                    sw3 = __hadd2(sw3, u32_to_h2(rw.w));
                    sb0 = __hadd2(sb0, u32_to_h2(rb.x));
                    sb1 = __hadd2(sb1, u32_to_h2(rb.y));
                    sb2 = __hadd2(sb2, u32_to_h2(rb.z));
                    sb3 = __hadd2(sb3, u32_to_h2(rb.w));
                }
                {
                    float2 f0 = __half22float2(sw0);
                    float2 f1 = __half22float2(sw1);
                    float2 f2 = __half22float2(sw2);
                    float2 f3 = __half22float2(sw3);
                    w0 += f0.x; w1 += f0.y; w2 += f1.x; w3 += f1.y;
                    w4 += f2.x; w5 += f2.y; w6 += f3.x; w7 += f3.y;
                }
                {
                    float2 f0 = __half22float2(sb0);
                    float2 f1 = __half22float2(sb1);
                    float2 f2 = __half22float2(sb2);
                    float2 f3 = __half22float2(sb3);
                    b0 += f0.x; b1 += f0.y; b2 += f1.x; b3 += f1.y;
                    b4 += f2.x; b5 += f2.y; b6 += f3.x; b7 += f3.y;
                }
            }

            float4 cw0 = make_float4(satf(w0+fbA.x), satf(w1+fbA.y),
                                     satf(w2+fbA.z), satf(w3+fbA.w));
            float4 cw1 = make_float4(satf(w4+fbB.x), satf(w5+fbB.y),
                                     satf(w6+fbB.z), satf(w7+fbB.w));
            float4 cb0 = make_float4(satf(b0+fbA.x), satf(b1+fbA.y),
                                     satf(b2+fbA.z), satf(b3+fbA.w));
            float4 cb1 = make_float4(satf(b4+fbB.x), satf(b5+fbB.y),
                                     satf(b6+fbB.z), satf(b7+fbB.w));

            const float s = stm[pos];
            const bool wfirst = (s > 0.5f);
            accp[2*lane]          = wfirst ? cw0 : cb0;
            accp[2*lane + 1]      = wfirst ? cw1 : cb1;
            accp[64 + 2*lane]     = wfirst ? cb0 : cw0;
            accp[64 + 2*lane + 1] = wfirst ? cb1 : cw1;
        }
        __syncwarp();

        // ---- L1: lane k computes output k for 4 positions; one fp16 weight
        //      load per j4 serves all 4 (f32x2 FMA) ----
        unsigned long long q00=0ull,q01=0ull, q10=0ull,q11=0ull;
        unsigned long long q20=0ull,q21=0ull, q30=0ull,q31=0ull;
        const ulonglong2* a0 = (const ulonglong2*)(accbase);
        const ulonglong2* a1 = (const ulonglong2*)(accbase + 128);
        const ulonglong2* a2 = (const ulonglong2*)(accbase + 256);
        const ulonglong2* a3 = (const ulonglong2*)(accbase + 384);
        #pragma unroll 4
        for (int j4 = 0; j4 < 128; j4++) {
            const uint2 wp = sh_w1h[j4 * 32 + lane];        // 2 wf, conflict-free
            const float2 wlo = __half22float2(u32_to_h2(wp.x));
            const float2 whi = __half22float2(u32_to_h2(wp.y));
            const unsigned long long W0 = pack_f32x2(wlo.x, wlo.y);
            const unsigned long long W1 = pack_f32x2(whi.x, whi.y);
            const ulonglong2 A0 = a0[j4];   // broadcasts, 1 wf each
            const ulonglong2 A1 = a1[j4];
            const ulonglong2 A2 = a2[j4];
            const ulonglong2 A3 = a3[j4];
            fma_f32x2(q00, A0.x, W0); fma_f32x2(q01, A0.y, W1);
            fma_f32x2(q10, A1.x, W0); fma_f32x2(q11, A1.y, W1);
            fma_f32x2(q20, A2.x, W0); fma_f32x2(q21, A2.y, W1);
            fma_f32x2(q30, A3.x, W0); fma_f32x2(q31, A3.y, W1);
        }
        float x1v[POSPW];
        x1v[0] = satf(f32x2_hsum(q00) + f32x2_hsum(q01) + l1b);
        x1v[1] = satf(f32x2_hsum(q10) + f32x2_hsum(q11) + l1b);
        x1v[2] = satf(f32x2_hsum(q20) + f32x2_hsum(q21) + l1b);
        x1v[3] = satf(f32x2_hsum(q30) + f32x2_hsum(q31) + l1b);
        __syncwarp();   // acc reads done before next group's stores

        // ---- L2 + L3 per position ----
        #pragma unroll 1
        for (int pp = 0; pp < POSPW; pp++) {
            const int pos = pbase + pp;
            if (pos >= B) break;
            const float x1 = x1v[pp];
            float s2 = l2b;
            #pragma unroll
            for (int j = 0; j < 32; j++) {
                const float xj = __shfl_sync(0xffffffffu, x1, j);
                s2 += xj * sh_l2t[j * 32 + lane];
            }
            const float x2 = satf(s2);
            float p = x2 * l3w;
            #pragma unroll
            for (int off = 16; off > 0; off >>= 1)
                p += __shfl_xor_sync(0xffffffffu, p, off);
            if (lane == 0)
                out[pos] = p + l3b;
        }
    }
}

extern "C" void kernel_launch(void* const* d_in, const int* in_sizes, int n_in,
                              void* d_out, int out_size)
{
    const int*   white_idx = (const int*)  d_in[0];
    const int*   black_idx = (const int*)  d_in[1];
    const float* stm       = (const float*)d_in[2];
    const float* ft_w      = (const float*)d_in[3];
    const float* ft_b      = (const float*)d_in[4];
    const float* l1_w      = (const float*)d_in[5];
    const float* l1_b      = (const float*)d_in[6];
    const float* l2_w      = (const float*)d_in[7];
    const float* l2_b      = (const float*)d_in[8];
    const float* l3_w      = (const float*)d_in[9];
    const float* l3_b      = (const float*)d_in[10];
    float* out = (float*)d_out;

    const int B = in_sizes[0] / ACTIVE;

    const int n_u4 = INPUTSZ * 32;
    convert_ftw_kernel<<<(n_u4 + 255) / 256, 256>>>(ft_w, n_u4);
    pack_l1w_kernel<<<(128 * 32 + 255) / 256, 256>>>(l1_w);

    cudaFuncSetAttribute(nnue_fused_kernel,
                         cudaFuncAttributeMaxDynamicSharedMemorySize,
                         (int)SMEM_BYTES);
    const int grid = 296;   // 2 CTAs/SM on 148 SMs
    nnue_fused_kernel<<<grid, NTHREADS, SMEM_BYTES>>>(
        white_idx, black_idx, stm, ft_b, l2_w,
        l1_b, l2_b, l3_w, l3_b, out, B);
}